// round 1
// baseline (speedup 1.0000x reference)
#include <cuda_runtime.h>
#include <cstdint>

// Problem constants (fixed shapes from reference)
#define T_TOK 8192          // B*S tokens
#define D_DIM 512
#define F_DIM 1024
#define E_NUM 8
#define K_TOP 2
#define NSLOT (T_TOK * K_TOP)   // 16384 (token, k-slot) pairs

// GEMM tiling
#define BM 128
#define BN 128
#define BK 32
#define NTHREADS 256
#define AS_STRIDE 36            // 32 + 4 pad -> A fragment LDS conflict-free
#define BS_STRIDE 136           // 128 + 8 pad -> B fragment LDS conflict-free
#define AS_BUF (BM * AS_STRIDE) // floats per A buffer
#define BS_BUF (BK * BS_STRIDE) // floats per B buffer
#define SMEM_BYTES ((2 * AS_BUF + 2 * BS_BUF) * 4 + BM * 4)

// -------- scratch (no cudaMalloc allowed: device globals) --------
__device__ int   g_slots[E_NUM][NSLOT];
__device__ int   g_cnt[E_NUM];
__device__ float g_H[(size_t)NSLOT * F_DIM];   // 64 MB intermediate
__device__ float g_Y[(size_t)NSLOT * D_DIM];   // 32 MB per-slot output

// -------- small helpers --------
__device__ __forceinline__ void cp_async16(uint32_t dst, const void* src) {
    asm volatile("cp.async.cg.shared.global [%0], [%1], 16;\n" :: "r"(dst), "l"(src));
}
__device__ __forceinline__ void cp_commit() { asm volatile("cp.async.commit_group;\n"); }
__device__ __forceinline__ void cp_wait0()  { asm volatile("cp.async.wait_group 0;\n"); }

__device__ __forceinline__ uint32_t f2tf32(float x) {
    uint32_t u;
    asm("cvt.rna.tf32.f32 %0, %1;\n" : "=r"(u) : "f"(x));
    return u;
}

__device__ __forceinline__ void mma_tf32(float c[4],
                                         uint32_t a0, uint32_t a1, uint32_t a2, uint32_t a3,
                                         uint32_t b0, uint32_t b1) {
    asm volatile(
        "mma.sync.aligned.m16n8k8.row.col.f32.tf32.tf32.f32 "
        "{%0,%1,%2,%3},{%4,%5,%6,%7},{%8,%9},{%0,%1,%2,%3};\n"
        : "+f"(c[0]), "+f"(c[1]), "+f"(c[2]), "+f"(c[3])
        : "r"(a0), "r"(a1), "r"(a2), "r"(a3), "r"(b0), "r"(b1));
}

// jax.nn.gelu default = tanh approximation
__device__ __forceinline__ float gelu_tanh(float x) {
    float x3 = x * x * x;
    float t = tanhf(0.7978845608028654f * (x + 0.044715f * x3));
    return 0.5f * x * (1.0f + t);
}

// -------- routing --------
__global__ void zero_counts_kernel() {
    if (threadIdx.x < E_NUM) g_cnt[threadIdx.x] = 0;
}

__global__ void route_kernel(const int* __restrict__ idx) {
    int s = blockIdx.x * blockDim.x + threadIdx.x;
    if (s < NSLOT) {
        int e = idx[s];
        int p = atomicAdd(&g_cnt[e], 1);
        g_slots[e][p] = s;
    }
}

// -------- grouped gather-GEMM --------
// PHASE 1: A = hidden rows gathered by slot (token = slot>>1), B = W1[e] [D,F],
//          out = g_H[slot, :] = gelu(A*B + b1[e])
// PHASE 2: A = g_H rows (row = slot), B = W2[e] [F,D],
//          out = g_Y[slot, :] = A*B + b2[e]
template <int PHASE>
__global__ __launch_bounds__(NTHREADS, 1)
void moe_gemm(const float* __restrict__ hidden,
              const float* __restrict__ Wbase,
              const float* __restrict__ bias) {
    constexpr int KDIM = (PHASE == 1) ? D_DIM : F_DIM;
    constexpr int NDIM = (PHASE == 1) ? F_DIM : D_DIM;

    const int e   = blockIdx.y;
    const int cnt = g_cnt[e];
    const int m0  = blockIdx.x * BM;
    if (m0 >= cnt) return;                      // inactive tile: early exit
    const int n0  = blockIdx.z * BN;

    const float* __restrict__ W  = Wbase + (size_t)e * KDIM * NDIM;
    const float* __restrict__ bv = bias + (size_t)e * NDIM;

    extern __shared__ float smem[];
    float* As = smem;                               // [2][AS_BUF]
    float* Bs = smem + 2 * AS_BUF;                  // [2][BS_BUF]
    int*   srow = (int*)(smem + 2 * AS_BUF + 2 * BS_BUF);  // [BM]

    const int tid = threadIdx.x;
    if (tid < BM) {
        int gm = m0 + tid;
        srow[tid] = g_slots[e][min(gm, cnt - 1)];   // clamp (cnt >= 1 here)
    }
    __syncthreads();

    const uint32_t as_base = (uint32_t)__cvta_generic_to_shared(As);
    const uint32_t bs_base = (uint32_t)__cvta_generic_to_shared(Bs);

    auto load_tile = [&](int kt, int buf) {
        const int k0 = kt * BK;
        // A tile: BM x BK floats = 1024 float4 chunks
        #pragma unroll
        for (int it = 0; it < 4; ++it) {
            int c   = tid + it * NTHREADS;
            int row = c >> 3;
            int c4  = (c & 7) * 4;
            int s   = srow[row];
            const float* src = (PHASE == 1)
                ? (hidden + (size_t)(s >> 1) * D_DIM + k0 + c4)
                : (g_H    + (size_t)s * F_DIM        + k0 + c4);
            cp_async16(as_base + (uint32_t)(buf * AS_BUF + row * AS_STRIDE + c4) * 4, src);
        }
        // B tile: BK x BN floats = 1024 float4 chunks
        #pragma unroll
        for (int it = 0; it < 4; ++it) {
            int c   = tid + it * NTHREADS;
            int row = c >> 5;
            int c4  = (c & 31) * 4;
            const float* src = W + (size_t)(k0 + row) * NDIM + n0 + c4;
            cp_async16(bs_base + (uint32_t)(buf * BS_BUF + row * BS_STRIDE + c4) * 4, src);
        }
        cp_commit();
    };

    const int lane = tid & 31;
    const int warp = tid >> 5;
    const int wm   = (warp & 3) * 32;   // 4 warps along M
    const int wn   = (warp >> 2) * 64;  // 2 warps along N
    const int gid  = lane >> 2;         // group id (0..7)
    const int tig  = lane & 3;          // thread-in-group (0..3)

    float acc[2][8][4];
    #pragma unroll
    for (int i = 0; i < 2; ++i)
        #pragma unroll
        for (int j = 0; j < 8; ++j)
            #pragma unroll
            for (int r = 0; r < 4; ++r) acc[i][j][r] = 0.f;

    constexpr int KT = KDIM / BK;
    load_tile(0, 0);

    for (int kt = 0; kt < KT; ++kt) {
        const int buf = kt & 1;
        cp_wait0();
        __syncthreads();
        if (kt + 1 < KT) load_tile(kt + 1, buf ^ 1);   // overlaps compute below

        const float* Ab = As + buf * AS_BUF;
        const float* Bb = Bs + buf * BS_BUF;

        #pragma unroll
        for (int ks = 0; ks < BK / 8; ++ks) {
            uint32_t af[2][4];
            #pragma unroll
            for (int mf = 0; mf < 2; ++mf) {
                int r0 = wm + mf * 16 + gid;
                af[mf][0] = f2tf32(Ab[r0 * AS_STRIDE + ks * 8 + tig]);
                af[mf][1] = f2tf32(Ab[(r0 + 8) * AS_STRIDE + ks * 8 + tig]);
                af[mf][2] = f2tf32(Ab[r0 * AS_STRIDE + ks * 8 + tig + 4]);
                af[mf][3] = f2tf32(Ab[(r0 + 8) * AS_STRIDE + ks * 8 + tig + 4]);
            }
            uint32_t bf[8][2];
            #pragma unroll
            for (int nf = 0; nf < 8; ++nf) {
                int col = wn + nf * 8 + gid;
                bf[nf][0] = f2tf32(Bb[(ks * 8 + tig) * BS_STRIDE + col]);
                bf[nf][1] = f2tf32(Bb[(ks * 8 + tig + 4) * BS_STRIDE + col]);
            }
            #pragma unroll
            for (int mf = 0; mf < 2; ++mf)
                #pragma unroll
                for (int nf = 0; nf < 8; ++nf)
                    mma_tf32(acc[mf][nf], af[mf][0], af[mf][1], af[mf][2], af[mf][3],
                             bf[nf][0], bf[nf][1]);
        }
        __syncthreads();
    }

    // epilogue: bias (+ gelu for PHASE 1), scatter to per-slot row
    #pragma unroll
    for (int mf = 0; mf < 2; ++mf) {
        #pragma unroll
        for (int rr = 0; rr < 2; ++rr) {
            int rloc = wm + mf * 16 + gid + rr * 8;
            int gm   = m0 + rloc;
            if (gm < cnt) {
                int s = srow[rloc];
                float* __restrict__ orow = (PHASE == 1)
                    ? (g_H + (size_t)s * F_DIM)
                    : (g_Y + (size_t)s * D_DIM);
                #pragma unroll
                for (int nf = 0; nf < 8; ++nf) {
                    int col = n0 + wn + nf * 8 + tig * 2;
                    float v0 = acc[mf][nf][rr * 2 + 0] + bv[col];
                    float v1 = acc[mf][nf][rr * 2 + 1] + bv[col + 1];
                    if (PHASE == 1) { v0 = gelu_tanh(v0); v1 = gelu_tanh(v1); }
                    *(float2*)(orow + col) = make_float2(v0, v1);
                }
            }
        }
    }
}

// -------- final combine: out[t] = w[t,0]*Y[2t] + w[t,1]*Y[2t+1] --------
__global__ void combine_kernel(const float* __restrict__ w, float* __restrict__ out) {
    int i = blockIdx.x * blockDim.x + threadIdx.x;
    const int n4 = T_TOK * D_DIM / 4;
    if (i >= n4) return;
    int t  = i / (D_DIM / 4);
    int c4 = i % (D_DIM / 4);
    float w0 = w[t * K_TOP + 0];
    float w1 = w[t * K_TOP + 1];
    const float4* Y = (const float4*)g_Y;
    float4 y0 = Y[(size_t)(t * K_TOP + 0) * (D_DIM / 4) + c4];
    float4 y1 = Y[(size_t)(t * K_TOP + 1) * (D_DIM / 4) + c4];
    float4 o;
    o.x = w0 * y0.x + w1 * y1.x;
    o.y = w0 * y0.y + w1 * y1.y;
    o.z = w0 * y0.z + w1 * y1.z;
    o.w = w0 * y0.w + w1 * y1.w;
    ((float4*)out)[i] = o;
}

extern "C" void kernel_launch(void* const* d_in, const int* in_sizes, int n_in,
                              void* d_out, int out_size) {
    const float* hidden = (const float*)d_in[0];   // [B,S,D] f32
    const int*   idx    = (const int*)d_in[1];     // [B,S,K] i32
    const float* wts    = (const float*)d_in[2];   // [B,S,K] f32
    const float* W1     = (const float*)d_in[3];   // [E,D,F]
    const float* b1     = (const float*)d_in[4];   // [E,F]
    const float* W2     = (const float*)d_in[5];   // [E,F,D]
    const float* b2     = (const float*)d_in[6];   // [E,D]
    float*       out    = (float*)d_out;           // [B,S,D] f32

    (void)in_sizes; (void)n_in; (void)out_size;

    // opt-in smem (idempotent; safe during graph capture)
    cudaFuncSetAttribute(moe_gemm<1>, cudaFuncAttributeMaxDynamicSharedMemorySize, SMEM_BYTES);
    cudaFuncSetAttribute(moe_gemm<2>, cudaFuncAttributeMaxDynamicSharedMemorySize, SMEM_BYTES);

    zero_counts_kernel<<<1, 32>>>();
    route_kernel<<<NSLOT / 256, 256>>>(idx);

    dim3 blk(NTHREADS);
    // phase 1: [n_e, D] x [D, F] -> H     (grid.x covers worst-case tiles; early exit)
    moe_gemm<1><<<dim3(NSLOT / BM, E_NUM, F_DIM / BN), blk, SMEM_BYTES>>>(hidden, W1, b1);
    // phase 2: [n_e, F] x [F, D] -> Y
    moe_gemm<2><<<dim3(NSLOT / BM, E_NUM, D_DIM / BN), blk, SMEM_BYTES>>>(hidden, W2, b2);

    combine_kernel<<<(T_TOK * D_DIM / 4 + 255) / 256, 256>>>(wts, out);
}

// round 3
// speedup vs baseline: 1.6134x; 1.6134x over previous
#include <cuda_runtime.h>
#include <cuda_fp16.h>
#include <cstdint>

// ---------------- problem constants ----------------
#define T_TOK 8192
#define D_DIM 512
#define F_DIM 1024
#define E_NUM 8
#define K_TOP 2
#define NSLOT (T_TOK * K_TOP)      // 16384 slots

// ---------------- GEMM tiling ----------------
#define BM 128
#define BN 256
#define BK 64                       // 64 fp16 = 128B A-rows
#define NSTAGE 3
#define NTHREADS 256
#define A_STAGE_BYTES (BM * 128)    // 16 KB
#define B_STAGE_BYTES (BK * 512)    // 32 KB (BK rows x BN fp16 = 512B rows)
#define SMEM_BYTES (NSTAGE * (A_STAGE_BYTES + B_STAGE_BYTES))   // 144 KB

// ---------------- device scratch (no cudaMalloc allowed) ----------------
__device__ int    g_slots[E_NUM][NSLOT];
__device__ int    g_cnt[E_NUM];
__device__ __half g_Xh[(size_t)T_TOK * D_DIM];              // 8 MB  hidden fp16
__device__ __half g_H[(size_t)NSLOT * F_DIM];               // 32 MB intermediate fp16
__device__ __half g_W1h[(size_t)E_NUM * D_DIM * F_DIM];     // 8 MB  [E][D][F] (k-major rows = n)
__device__ __half g_W2h[(size_t)E_NUM * F_DIM * D_DIM];     // 8 MB  [E][F][D]

// ---------------- PTX helpers ----------------
__device__ __forceinline__ uint32_t smem_u32(const void* p) {
    uint32_t a;
    asm("{ .reg .u64 t; cvta.to.shared.u64 t, %1; cvt.u32.u64 %0, t; }" : "=r"(a) : "l"(p));
    return a;
}
__device__ __forceinline__ void cp_async16(uint32_t dst, const void* src) {
    asm volatile("cp.async.cg.shared.global [%0], [%1], 16;\n" :: "r"(dst), "l"(src));
}
__device__ __forceinline__ void cp_commit() { asm volatile("cp.async.commit_group;\n"); }
template <int N>
__device__ __forceinline__ void cp_wait() {
    asm volatile("cp.async.wait_group %0;\n" :: "n"(N) : "memory");
}
__device__ __forceinline__ void ldsm_x4(uint32_t* r, uint32_t addr) {
    asm volatile("ldmatrix.sync.aligned.m8n8.x4.shared.b16 {%0,%1,%2,%3}, [%4];"
                 : "=r"(r[0]), "=r"(r[1]), "=r"(r[2]), "=r"(r[3]) : "r"(addr));
}
__device__ __forceinline__ void ldsm_x4_trans(uint32_t* r, uint32_t addr) {
    asm volatile("ldmatrix.sync.aligned.m8n8.x4.trans.shared.b16 {%0,%1,%2,%3}, [%4];"
                 : "=r"(r[0]), "=r"(r[1]), "=r"(r[2]), "=r"(r[3]) : "r"(addr));
}
__device__ __forceinline__ void mma_fp16(float c[4], const uint32_t a[4],
                                         uint32_t b0, uint32_t b1) {
    asm volatile(
        "mma.sync.aligned.m16n8k16.row.col.f32.f16.f16.f32 "
        "{%0,%1,%2,%3},{%4,%5,%6,%7},{%8,%9},{%0,%1,%2,%3};\n"
        : "+f"(c[0]), "+f"(c[1]), "+f"(c[2]), "+f"(c[3])
        : "r"(a[0]), "r"(a[1]), "r"(a[2]), "r"(a[3]), "r"(b0), "r"(b1));
}
__device__ __forceinline__ void red_add_v2(float* p, float v0, float v1) {
    asm volatile("red.relaxed.gpu.global.add.v2.f32 [%0], {%1,%2};"
                 :: "l"(p), "f"(v0), "f"(v1) : "memory");
}

__device__ __forceinline__ float gelu_tanh(float x) {
    float x3 = x * x * x;
    float t = tanhf(0.7978845608028654f * (x + 0.044715f * x3));
    return 0.5f * x * (1.0f + t);
}

// ---------------- routing / setup ----------------
__global__ void zero_counts_kernel() {
    if (threadIdx.x < E_NUM) g_cnt[threadIdx.x] = 0;
}
__global__ void route_kernel(const int* __restrict__ idx) {
    int s = blockIdx.x * blockDim.x + threadIdx.x;
    if (s < NSLOT) {
        int e = idx[s];
        int p = atomicAdd(&g_cnt[e], 1);
        g_slots[e][p] = s;
    }
}
__global__ void zero_out_kernel(float* __restrict__ out) {
    int i = blockIdx.x * blockDim.x + threadIdx.x;
    if (i < T_TOK * D_DIM / 4) ((float4*)out)[i] = make_float4(0.f, 0.f, 0.f, 0.f);
}
// fp32 -> fp16, 4 elems/thread
__global__ void f32tof16_kernel(const float* __restrict__ src, __half* __restrict__ dst, int n4) {
    int i = blockIdx.x * blockDim.x + threadIdx.x;
    if (i < n4) {
        float4 v = ((const float4*)src)[i];
        __half2* d = (__half2*)dst;
        d[2 * i + 0] = __floats2half2_rn(v.x, v.y);
        d[2 * i + 1] = __floats2half2_rn(v.z, v.w);
    }
}

// ---------------- fp16 mma.sync grouped gather-GEMM ----------------
// PHASE 1: A = g_Xh[slot>>1] (K=D), B = g_W1h[e] [D][F] row-major(k,n)
//          -> g_H[slot] = fp16(gelu(A*B + b1))
// PHASE 2: A = g_H[slot]    (K=F), B = g_W2h[e] [F][D]
//          -> out[token] += w * (A*B + b2)   (red.v2.f32)
template <int PHASE>
__global__ __launch_bounds__(NTHREADS, 1)
void moe_gemm_fp16(const float* __restrict__ bias,
                   const float* __restrict__ wts,
                   float* __restrict__ out) {
    constexpr int KDIM = (PHASE == 1) ? D_DIM : F_DIM;
    constexpr int NDIM = (PHASE == 1) ? F_DIM : D_DIM;
    constexpr int KT   = KDIM / BK;

    const int e   = blockIdx.y;
    const int cnt = g_cnt[e];
    const int m0  = blockIdx.x * BM;
    if (m0 >= cnt) return;
    const int n0  = blockIdx.z * BN;

    const __half* __restrict__ W =
        ((PHASE == 1) ? g_W1h : g_W2h) + (size_t)e * KDIM * NDIM;

    extern __shared__ __align__(1024) char dsm[];
    const uint32_t sbase = smem_u32(dsm);
    // A stage s at sbase + s*16KB ; B stage s at sbase + NSTAGE*16KB + s*32KB
    const uint32_t bbase0 = sbase + NSTAGE * A_STAGE_BYTES;

    __shared__ int s_srow[BM];

    const int tid  = threadIdx.x;
    const int wid  = tid >> 5;
    const int lane = tid & 31;

    if (tid < BM) s_srow[tid] = g_slots[e][min(m0 + tid, cnt - 1)];
    __syncthreads();

    auto load_stage = [&](int kt) {
        const int s = kt % NSTAGE;
        const uint32_t abuf = sbase + (uint32_t)s * A_STAGE_BYTES;
        const uint32_t bbuf = bbase0 + (uint32_t)s * B_STAGE_BYTES;
        const int k0 = kt * BK;
        // A: 128 rows x 8 chunks of 16B
        #pragma unroll
        for (int it = 0; it < 4; ++it) {
            const int c  = tid + it * NTHREADS;      // 0..1023
            const int r  = c >> 3;
            const int ch = c & 7;
            const int slot = s_srow[r];
            const __half* asrc = (PHASE == 1)
                ? g_Xh + (size_t)(slot >> 1) * D_DIM + k0 + ch * 8
                : g_H  + (size_t)slot * F_DIM        + k0 + ch * 8;
            cp_async16(abuf + (uint32_t)(r * 128 + ((ch ^ (r & 7)) << 4)), asrc);
        }
        // B: 64 k-rows x 32 chunks of 16B (512B rows)
        #pragma unroll
        for (int it = 0; it < 8; ++it) {
            const int c  = tid + it * NTHREADS;      // 0..2047
            const int r  = c >> 5;
            const int ch = c & 31;
            const __half* bsrc = W + (size_t)(k0 + r) * NDIM + n0 + ch * 8;
            cp_async16(bbuf + (uint32_t)(r * 512 + ((ch ^ (r & 7)) << 4)), bsrc);
        }
        cp_commit();
    };

    // warp layout: 2 (m) x 4 (n) warps of 64x64
    const int wm = (wid & 1) * 64;
    const int wn = (wid >> 1) * 64;
    const int rA = lane & 15;          // ldmatrix row-within-16
    const int cl = lane >> 4;          // chunk select (0/1)

    float acc[4][8][4];
    #pragma unroll
    for (int i = 0; i < 4; ++i)
        #pragma unroll
        for (int j = 0; j < 8; ++j)
            #pragma unroll
            for (int r = 0; r < 4; ++r) acc[i][j][r] = 0.f;

    load_stage(0);
    load_stage(1);

    for (int kt = 0; kt < KT; ++kt) {
        if (kt + 2 < KT) load_stage(kt + 2);
        if (kt + 2 < KT)      { cp_wait<2>(); }
        else if (kt + 1 < KT) { cp_wait<1>(); }
        else                  { cp_wait<0>(); }
        __syncthreads();

        const int s = kt % NSTAGE;
        const uint32_t abuf = sbase + (uint32_t)s * A_STAGE_BYTES;
        const uint32_t bbuf = bbase0 + (uint32_t)s * B_STAGE_BYTES;

        #pragma unroll
        for (int ks = 0; ks < BK / 16; ++ks) {
            // A fragments: 4 x ldmatrix.x4 (m16k16 each)
            uint32_t af[4][4];
            #pragma unroll
            for (int mf = 0; mf < 4; ++mf) {
                const int r = wm + mf * 16 + rA;
                const int chA = ks * 2 + cl;
                ldsm_x4(af[mf], abuf + (uint32_t)(r * 128 + ((chA ^ (r & 7)) << 4)));
            }
            // B fragments: 4 x ldmatrix.x4.trans (n16k16 each)
            uint32_t bf[4][4];
            #pragma unroll
            for (int nf16 = 0; nf16 < 4; ++nf16) {
                const int r = ks * 16 + rA;            // k row
                const int chB = (wn >> 3) + nf16 * 2 + cl;
                ldsm_x4_trans(bf[nf16], bbuf + (uint32_t)(r * 512 + ((chB ^ (r & 7)) << 4)));
            }
            #pragma unroll
            for (int mf = 0; mf < 4; ++mf)
                #pragma unroll
                for (int nf = 0; nf < 8; ++nf) {
                    const int g = nf >> 1;
                    const int h = (nf & 1) * 2;        // 0 -> {r0,r1}, 1 -> {r2,r3}
                    mma_fp16(acc[mf][nf], af[mf], bf[g][h], bf[g][h + 1]);
                }
        }
        __syncthreads();
    }

    // ---------------- epilogue (acc already in registers) ----------------
    const int rbase = wm + (lane >> 2);
    const int cbase = wn + 2 * (lane & 3);
    #pragma unroll
    for (int mf = 0; mf < 4; ++mf) {
        #pragma unroll
        for (int half = 0; half < 2; ++half) {      // c0,c1 vs c2,c3 (row +8)
            const int rloc = rbase + mf * 16 + half * 8;
            const int gm   = m0 + rloc;
            if (gm < cnt) {
                const int slot = s_srow[rloc];
                if (PHASE == 1) {
                    __half* __restrict__ orow = g_H + (size_t)slot * F_DIM + n0;
                    #pragma unroll
                    for (int nf = 0; nf < 8; ++nf) {
                        const int col = cbase + nf * 8;
                        float v0 = gelu_tanh(acc[mf][nf][half * 2 + 0] + __ldg(bias + (size_t)e * NDIM + n0 + col));
                        float v1 = gelu_tanh(acc[mf][nf][half * 2 + 1] + __ldg(bias + (size_t)e * NDIM + n0 + col + 1));
                        *(__half2*)(orow + col) = __floats2half2_rn(v0, v1);
                    }
                } else {
                    const float w = __ldg(wts + slot);
                    float* __restrict__ orow = out + (size_t)(slot >> 1) * D_DIM + n0;
                    #pragma unroll
                    for (int nf = 0; nf < 8; ++nf) {
                        const int col = cbase + nf * 8;
                        float v0 = (acc[mf][nf][half * 2 + 0] + __ldg(bias + (size_t)e * NDIM + n0 + col))     * w;
                        float v1 = (acc[mf][nf][half * 2 + 1] + __ldg(bias + (size_t)e * NDIM + n0 + col + 1)) * w;
                        red_add_v2(orow + col, v0, v1);
                    }
                }
            }
        }
    }
}

// ---------------- launch ----------------
extern "C" void kernel_launch(void* const* d_in, const int* in_sizes, int n_in,
                              void* d_out, int out_size) {
    const float* hidden = (const float*)d_in[0];
    const int*   idx    = (const int*)d_in[1];
    const float* wts    = (const float*)d_in[2];
    const float* W1     = (const float*)d_in[3];
    const float* b1     = (const float*)d_in[4];
    const float* W2     = (const float*)d_in[5];
    const float* b2     = (const float*)d_in[6];
    float*       out    = (float*)d_out;
    (void)in_sizes; (void)n_in; (void)out_size;

    cudaFuncSetAttribute(moe_gemm_fp16<1>, cudaFuncAttributeMaxDynamicSharedMemorySize, SMEM_BYTES);
    cudaFuncSetAttribute(moe_gemm_fp16<2>, cudaFuncAttributeMaxDynamicSharedMemorySize, SMEM_BYTES);

    zero_counts_kernel<<<1, 32>>>();
    route_kernel<<<NSLOT / 256, 256>>>(idx);

    // one-time fp32 -> fp16 conversions (layouts preserved)
    {
        __half* dXh; cudaGetSymbolAddress((void**)&dXh, g_Xh);
        __half* dW1; cudaGetSymbolAddress((void**)&dW1, g_W1h);
        __half* dW2; cudaGetSymbolAddress((void**)&dW2, g_W2h);
        const int nx = T_TOK * D_DIM / 4;
        const int nw = E_NUM * D_DIM * F_DIM / 4;
        f32tof16_kernel<<<(nx + 255) / 256, 256>>>(hidden, dXh, nx);
        f32tof16_kernel<<<(nw + 255) / 256, 256>>>(W1, dW1, nw);
        f32tof16_kernel<<<(nw + 255) / 256, 256>>>(W2, dW2, nw);
    }
    zero_out_kernel<<<(T_TOK * D_DIM / 4 + 255) / 256, 256>>>(out);

    // phase 1: K=512, N=1024 (4 n-tiles)
    moe_gemm_fp16<1><<<dim3(NSLOT / BM, E_NUM, F_DIM / BN), NTHREADS, SMEM_BYTES>>>(b1, nullptr, nullptr);
    // phase 2: K=1024, N=512 (2 n-tiles), fused weighted combine
    moe_gemm_fp16<2><<<dim3(NSLOT / BM, E_NUM, D_DIM / BN), NTHREADS, SMEM_BYTES>>>(b2, wts, out);
}

// round 4
// speedup vs baseline: 1.7173x; 1.0644x over previous
#include <cuda_runtime.h>
#include <cuda_fp16.h>
#include <cstdint>

// ---------------- problem constants ----------------
#define T_TOK 8192
#define D_DIM 512
#define F_DIM 1024
#define E_NUM 8
#define K_TOP 2
#define NSLOT (T_TOK * K_TOP)      // 16384 slots

// ---------------- GEMM tiling ----------------
#define BM 128
#define BN 256
#define BK 64                       // 64 fp16 = 128B A-rows
#define NSTAGE 3
#define NTHREADS 512                // 16 warps: 2(m) x 8(n) of 64x32
#define NCTA 148                    // persistent grid
#define A_STAGE_BYTES (BM * 128)    // 16 KB
#define B_STAGE_BYTES (BK * 512)    // 32 KB
#define SMEM_BYTES (NSTAGE * (A_STAGE_BYTES + B_STAGE_BYTES))   // 144 KB

// ---------------- device scratch (no cudaMalloc allowed) ----------------
__device__ int    g_slots[E_NUM][NSLOT];
__device__ int    g_cnt[E_NUM];
__device__ __half g_Xh[(size_t)T_TOK * D_DIM];              // 8 MB
__device__ __half g_H[(size_t)NSLOT * F_DIM];               // 32 MB
__device__ __half g_W1h[(size_t)E_NUM * D_DIM * F_DIM];     // 8 MB [E][D][F]
__device__ __half g_W2h[(size_t)E_NUM * F_DIM * D_DIM];     // 8 MB [E][F][D]

// ---------------- PTX helpers ----------------
__device__ __forceinline__ uint32_t smem_u32(const void* p) {
    uint32_t a;
    asm("{ .reg .u64 t; cvta.to.shared.u64 t, %1; cvt.u32.u64 %0, t; }" : "=r"(a) : "l"(p));
    return a;
}
__device__ __forceinline__ void cp_async16(uint32_t dst, const void* src) {
    asm volatile("cp.async.cg.shared.global [%0], [%1], 16;\n" :: "r"(dst), "l"(src));
}
__device__ __forceinline__ void cp_commit() { asm volatile("cp.async.commit_group;\n"); }
template <int N>
__device__ __forceinline__ void cp_wait() {
    asm volatile("cp.async.wait_group %0;\n" :: "n"(N) : "memory");
}
__device__ __forceinline__ void ldsm_x4(uint32_t* r, uint32_t addr) {
    asm volatile("ldmatrix.sync.aligned.m8n8.x4.shared.b16 {%0,%1,%2,%3}, [%4];"
                 : "=r"(r[0]), "=r"(r[1]), "=r"(r[2]), "=r"(r[3]) : "r"(addr));
}
__device__ __forceinline__ void ldsm_x4_trans(uint32_t* r, uint32_t addr) {
    asm volatile("ldmatrix.sync.aligned.m8n8.x4.trans.shared.b16 {%0,%1,%2,%3}, [%4];"
                 : "=r"(r[0]), "=r"(r[1]), "=r"(r[2]), "=r"(r[3]) : "r"(addr));
}
__device__ __forceinline__ void mma_fp16(float c[4], const uint32_t a[4],
                                         uint32_t b0, uint32_t b1) {
    asm volatile(
        "mma.sync.aligned.m16n8k16.row.col.f32.f16.f16.f32 "
        "{%0,%1,%2,%3},{%4,%5,%6,%7},{%8,%9},{%0,%1,%2,%3};\n"
        : "+f"(c[0]), "+f"(c[1]), "+f"(c[2]), "+f"(c[3])
        : "r"(a[0]), "r"(a[1]), "r"(a[2]), "r"(a[3]), "r"(b0), "r"(b1));
}
__device__ __forceinline__ void red_add_v2(float* p, float v0, float v1) {
    asm volatile("red.relaxed.gpu.global.add.v2.f32 [%0], {%1,%2};"
                 :: "l"(p), "f"(v0), "f"(v1) : "memory");
}

__device__ __forceinline__ float gelu_tanh(float x) {
    float x3 = x * x * x;
    float t = tanhf(0.7978845608028654f * (x + 0.044715f * x3));
    return 0.5f * x * (1.0f + t);
}

// ---------------- routing / setup ----------------
__global__ void zero_counts_kernel() {
    if (threadIdx.x < E_NUM) g_cnt[threadIdx.x] = 0;
}
__global__ void route_kernel(const int* __restrict__ idx) {
    int s = blockIdx.x * blockDim.x + threadIdx.x;
    if (s < NSLOT) {
        int e = idx[s];
        int p = atomicAdd(&g_cnt[e], 1);
        g_slots[e][p] = s;
    }
}
// fused prep: convert hidden/W1/W2 to fp16 and zero the output (all float4-granular)
#define NX4 (T_TOK * D_DIM / 4)
#define NW4 (E_NUM * D_DIM * F_DIM / 4)
__global__ void prep_kernel(const float* __restrict__ hidden,
                            const float* __restrict__ W1,
                            const float* __restrict__ W2,
                            float* __restrict__ out) {
    const int i = blockIdx.x * blockDim.x + threadIdx.x;
    const int total = NX4 + 2 * NW4 + NX4;   // converts + zero_out
    if (i >= total) return;
    if (i < NX4) {
        float4 v = ((const float4*)hidden)[i];
        ((__half2*)g_Xh)[2 * i + 0] = __floats2half2_rn(v.x, v.y);
        ((__half2*)g_Xh)[2 * i + 1] = __floats2half2_rn(v.z, v.w);
    } else if (i < NX4 + NW4) {
        int j = i - NX4;
        float4 v = ((const float4*)W1)[j];
        ((__half2*)g_W1h)[2 * j + 0] = __floats2half2_rn(v.x, v.y);
        ((__half2*)g_W1h)[2 * j + 1] = __floats2half2_rn(v.z, v.w);
    } else if (i < NX4 + 2 * NW4) {
        int j = i - NX4 - NW4;
        float4 v = ((const float4*)W2)[j];
        ((__half2*)g_W2h)[2 * j + 0] = __floats2half2_rn(v.x, v.y);
        ((__half2*)g_W2h)[2 * j + 1] = __floats2half2_rn(v.z, v.w);
    } else {
        int j = i - NX4 - 2 * NW4;
        ((float4*)out)[j] = make_float4(0.f, 0.f, 0.f, 0.f);
    }
}

// ---------------- persistent fp16 grouped gather-GEMM ----------------
// PHASE 1: A = g_Xh[slot>>1] (K=D), B = g_W1h[e] -> g_H[slot] = fp16(gelu(A*B + b1))
// PHASE 2: A = g_H[slot]     (K=F), B = g_W2h[e] -> out[token] += w*(A*B + b2)
template <int PHASE>
__global__ __launch_bounds__(NTHREADS, 1)
void moe_gemm_fp16(const float* __restrict__ bias,
                   const float* __restrict__ wts,
                   float* __restrict__ out) {
    constexpr int KDIM = (PHASE == 1) ? D_DIM : F_DIM;
    constexpr int NDIM = (PHASE == 1) ? F_DIM : D_DIM;
    constexpr int KT   = KDIM / BK;
    constexpr int NT   = NDIM / BN;

    extern __shared__ __align__(1024) char dsm[];
    const uint32_t sbase  = smem_u32(dsm);
    const uint32_t bbase0 = sbase + NSTAGE * A_STAGE_BYTES;

    __shared__ int s_srow[BM];

    const int tid  = threadIdx.x;
    const int wid  = tid >> 5;
    const int lane = tid & 31;
    const int wm = (wid & 1) * 64;
    const int wn = (wid >> 1) * 32;
    const int rA = lane & 15;
    const int cl = lane >> 4;

    // runtime tile enumeration from g_cnt
    int tcnt[E_NUM], tbeg[E_NUM];
    int total_tiles = 0;
    #pragma unroll
    for (int e = 0; e < E_NUM; ++e) {
        tbeg[e] = total_tiles;
        tcnt[e] = g_cnt[e];
        total_tiles += ((tcnt[e] + BM - 1) / BM) * NT;
    }

    for (int tile = blockIdx.x; tile < total_tiles; tile += NCTA) {
        // map tile -> (e, m0, n0)
        int e = 0;
        #pragma unroll
        for (int q = 1; q < E_NUM; ++q) if (tile >= tbeg[q]) e = q;
        const int local = tile - tbeg[e];
        const int cnt   = tcnt[e];
        const int m0    = (local / NT) * BM;
        const int n0    = (local % NT) * BN;

        const __half* __restrict__ W =
            ((PHASE == 1) ? g_W1h : g_W2h) + (size_t)e * KDIM * NDIM;

        __syncthreads();   // protect s_srow reuse across tiles
        if (tid < BM) s_srow[tid] = g_slots[e][min(m0 + tid, cnt - 1)];
        __syncthreads();

        auto load_stage = [&](int kt) {
            const int s = kt % NSTAGE;
            const uint32_t abuf = sbase + (uint32_t)s * A_STAGE_BYTES;
            const uint32_t bbuf = bbase0 + (uint32_t)s * B_STAGE_BYTES;
            const int k0 = kt * BK;
            #pragma unroll
            for (int it = 0; it < 2; ++it) {           // A: 1024 chunks / 512 thr
                const int c  = tid + it * NTHREADS;
                const int r  = c >> 3;
                const int ch = c & 7;
                const int slot = s_srow[r];
                const __half* asrc = (PHASE == 1)
                    ? g_Xh + (size_t)(slot >> 1) * D_DIM + k0 + ch * 8
                    : g_H  + (size_t)slot * F_DIM        + k0 + ch * 8;
                cp_async16(abuf + (uint32_t)(r * 128 + ((ch ^ (r & 7)) << 4)), asrc);
            }
            #pragma unroll
            for (int it = 0; it < 4; ++it) {           // B: 2048 chunks / 512 thr
                const int c  = tid + it * NTHREADS;
                const int r  = c >> 5;
                const int ch = c & 31;
                const __half* bsrc = W + (size_t)(k0 + r) * NDIM + n0 + ch * 8;
                cp_async16(bbuf + (uint32_t)(r * 512 + ((ch ^ (r & 7)) << 4)), bsrc);
            }
            cp_commit();
        };

        float acc[4][4][4];
        #pragma unroll
        for (int i = 0; i < 4; ++i)
            #pragma unroll
            for (int j = 0; j < 4; ++j)
                #pragma unroll
                for (int r = 0; r < 4; ++r) acc[i][j][r] = 0.f;

        load_stage(0);
        load_stage(1);

        for (int kt = 0; kt < KT; ++kt) {
            if (kt + 2 < KT) load_stage(kt + 2);
            if (kt + 2 < KT)      { cp_wait<2>(); }
            else if (kt + 1 < KT) { cp_wait<1>(); }
            else                  { cp_wait<0>(); }
            __syncthreads();

            const int s = kt % NSTAGE;
            const uint32_t abuf = sbase + (uint32_t)s * A_STAGE_BYTES;
            const uint32_t bbuf = bbase0 + (uint32_t)s * B_STAGE_BYTES;

            #pragma unroll
            for (int ks = 0; ks < BK / 16; ++ks) {
                uint32_t af[4][4];
                #pragma unroll
                for (int mf = 0; mf < 4; ++mf) {
                    const int r = wm + mf * 16 + rA;
                    const int chA = ks * 2 + cl;
                    ldsm_x4(af[mf], abuf + (uint32_t)(r * 128 + ((chA ^ (r & 7)) << 4)));
                }
                uint32_t bf[2][4];
                #pragma unroll
                for (int nf16 = 0; nf16 < 2; ++nf16) {
                    const int r = ks * 16 + rA;
                    const int chB = (wn >> 3) + nf16 * 2 + cl;
                    ldsm_x4_trans(bf[nf16], bbuf + (uint32_t)(r * 512 + ((chB ^ (r & 7)) << 4)));
                }
                #pragma unroll
                for (int mf = 0; mf < 4; ++mf)
                    #pragma unroll
                    for (int nf = 0; nf < 4; ++nf) {
                        const int g = nf >> 1;
                        const int h = (nf & 1) * 2;
                        mma_fp16(acc[mf][nf], af[mf], bf[g][h], bf[g][h + 1]);
                    }
            }
            __syncthreads();
        }

        // ---------------- epilogue ----------------
        const int rbase = wm + (lane >> 2);
        const int cbase = wn + 2 * (lane & 3);
        #pragma unroll
        for (int mf = 0; mf < 4; ++mf) {
            #pragma unroll
            for (int half = 0; half < 2; ++half) {
                const int rloc = rbase + mf * 16 + half * 8;
                const int gm   = m0 + rloc;
                if (gm < cnt) {
                    const int slot = s_srow[rloc];
                    if (PHASE == 1) {
                        __half* __restrict__ orow = g_H + (size_t)slot * F_DIM + n0;
                        #pragma unroll
                        for (int nf = 0; nf < 4; ++nf) {
                            const int col = cbase + nf * 8;
                            float v0 = gelu_tanh(acc[mf][nf][half * 2 + 0] +
                                                 __ldg(bias + (size_t)e * NDIM + n0 + col));
                            float v1 = gelu_tanh(acc[mf][nf][half * 2 + 1] +
                                                 __ldg(bias + (size_t)e * NDIM + n0 + col + 1));
                            *(__half2*)(orow + col) = __floats2half2_rn(v0, v1);
                        }
                    } else {
                        const float w = __ldg(wts + slot);
                        float* __restrict__ orow = out + (size_t)(slot >> 1) * D_DIM + n0;
                        #pragma unroll
                        for (int nf = 0; nf < 4; ++nf) {
                            const int col = cbase + nf * 8;
                            float v0 = (acc[mf][nf][half * 2 + 0] +
                                        __ldg(bias + (size_t)e * NDIM + n0 + col)) * w;
                            float v1 = (acc[mf][nf][half * 2 + 1] +
                                        __ldg(bias + (size_t)e * NDIM + n0 + col + 1)) * w;
                            red_add_v2(orow + col, v0, v1);
                        }
                    }
                }
            }
        }
    }
}

// ---------------- launch ----------------
extern "C" void kernel_launch(void* const* d_in, const int* in_sizes, int n_in,
                              void* d_out, int out_size) {
    const float* hidden = (const float*)d_in[0];
    const int*   idx    = (const int*)d_in[1];
    const float* wts    = (const float*)d_in[2];
    const float* W1     = (const float*)d_in[3];
    const float* b1     = (const float*)d_in[4];
    const float* W2     = (const float*)d_in[5];
    const float* b2     = (const float*)d_in[6];
    float*       out    = (float*)d_out;
    (void)in_sizes; (void)n_in; (void)out_size;

    cudaFuncSetAttribute(moe_gemm_fp16<1>, cudaFuncAttributeMaxDynamicSharedMemorySize, SMEM_BYTES);
    cudaFuncSetAttribute(moe_gemm_fp16<2>, cudaFuncAttributeMaxDynamicSharedMemorySize, SMEM_BYTES);

    zero_counts_kernel<<<1, 32>>>();
    route_kernel<<<NSLOT / 256, 256>>>(idx);

    const int prep_total = NX4 + 2 * NW4 + NX4;
    prep_kernel<<<(prep_total + 255) / 256, 256>>>(hidden, W1, W2, out);

    moe_gemm_fp16<1><<<NCTA, NTHREADS, SMEM_BYTES>>>(b1, nullptr, nullptr);
    moe_gemm_fp16<2><<<NCTA, NTHREADS, SMEM_BYTES>>>(b2, wts, out);
}

// round 5
// speedup vs baseline: 1.8154x; 1.0571x over previous
#include <cuda_runtime.h>
#include <cuda_fp16.h>
#include <cstdint>

// ---------------- problem constants ----------------
#define T_TOK 8192
#define D_DIM 512
#define F_DIM 1024
#define E_NUM 8
#define K_TOP 2
#define NSLOT (T_TOK * K_TOP)      // 16384 slots

// ---------------- GEMM tiling ----------------
#define BM 128
#define BN 128
#define BK 64                       // 64 fp16 = 128B A-rows, B rows 256B
#define NSTAGE 3
#define NTHREADS 256                // 8 warps: 2(m) x 4(n) of 64x32
#define NCTA 296                    // persistent grid, 2 CTAs/SM
#define A_STAGE_BYTES (BM * 128)    // 16 KB
#define B_STAGE_BYTES (BK * 256)    // 16 KB
#define SMEM_BYTES (NSTAGE * (A_STAGE_BYTES + B_STAGE_BYTES))   // 96 KB

// ---------------- device scratch (no cudaMalloc allowed) ----------------
__device__ int    g_slots[E_NUM][NSLOT];
__device__ int    g_cnt[E_NUM];
__device__ __half g_Xh[(size_t)T_TOK * D_DIM];              // 8 MB
__device__ __half g_H[(size_t)NSLOT * F_DIM];               // 32 MB
__device__ __half g_W1h[(size_t)E_NUM * D_DIM * F_DIM];     // 8 MB [E][D][F]
__device__ __half g_W2h[(size_t)E_NUM * F_DIM * D_DIM];     // 8 MB [E][F][D]

// ---------------- PTX helpers ----------------
__device__ __forceinline__ uint32_t smem_u32(const void* p) {
    uint32_t a;
    asm("{ .reg .u64 t; cvta.to.shared.u64 t, %1; cvt.u32.u64 %0, t; }" : "=r"(a) : "l"(p));
    return a;
}
__device__ __forceinline__ void cp_async16(uint32_t dst, const void* src) {
    asm volatile("cp.async.cg.shared.global [%0], [%1], 16;\n" :: "r"(dst), "l"(src));
}
__device__ __forceinline__ void cp_commit() { asm volatile("cp.async.commit_group;\n"); }
template <int N>
__device__ __forceinline__ void cp_wait() {
    asm volatile("cp.async.wait_group %0;\n" :: "n"(N) : "memory");
}
__device__ __forceinline__ void ldsm_x4(uint32_t* r, uint32_t addr) {
    asm volatile("ldmatrix.sync.aligned.m8n8.x4.shared.b16 {%0,%1,%2,%3}, [%4];"
                 : "=r"(r[0]), "=r"(r[1]), "=r"(r[2]), "=r"(r[3]) : "r"(addr));
}
__device__ __forceinline__ void ldsm_x4_trans(uint32_t* r, uint32_t addr) {
    asm volatile("ldmatrix.sync.aligned.m8n8.x4.trans.shared.b16 {%0,%1,%2,%3}, [%4];"
                 : "=r"(r[0]), "=r"(r[1]), "=r"(r[2]), "=r"(r[3]) : "r"(addr));
}
__device__ __forceinline__ void mma_fp16(float c[4], const uint32_t a[4],
                                         uint32_t b0, uint32_t b1) {
    asm volatile(
        "mma.sync.aligned.m16n8k16.row.col.f32.f16.f16.f32 "
        "{%0,%1,%2,%3},{%4,%5,%6,%7},{%8,%9},{%0,%1,%2,%3};\n"
        : "+f"(c[0]), "+f"(c[1]), "+f"(c[2]), "+f"(c[3])
        : "r"(a[0]), "r"(a[1]), "r"(a[2]), "r"(a[3]), "r"(b0), "r"(b1));
}
__device__ __forceinline__ void red_add_v2(float* p, float v0, float v1) {
    asm volatile("red.relaxed.gpu.global.add.v2.f32 [%0], {%1,%2};"
                 :: "l"(p), "f"(v0), "f"(v1) : "memory");
}

__device__ __forceinline__ float gelu_tanh(float x) {
    float x3 = x * x * x;
    float t = tanhf(0.7978845608028654f * (x + 0.044715f * x3));
    return 0.5f * x * (1.0f + t);
}

// ---------------- routing / setup ----------------
__global__ void zero_counts_kernel() {
    if (threadIdx.x < E_NUM) g_cnt[threadIdx.x] = 0;
}
__global__ void route_kernel(const int* __restrict__ idx) {
    int s = blockIdx.x * blockDim.x + threadIdx.x;
    if (s < NSLOT) {
        int e = idx[s];
        int p = atomicAdd(&g_cnt[e], 1);
        g_slots[e][p] = s;
    }
}
// fused prep: convert hidden/W1/W2 to fp16 and zero the output
#define NX4 (T_TOK * D_DIM / 4)
#define NW4 (E_NUM * D_DIM * F_DIM / 4)
__global__ void prep_kernel(const float* __restrict__ hidden,
                            const float* __restrict__ W1,
                            const float* __restrict__ W2,
                            float* __restrict__ out) {
    const int i = blockIdx.x * blockDim.x + threadIdx.x;
    const int total = NX4 + 2 * NW4 + NX4;
    if (i >= total) return;
    if (i < NX4) {
        float4 v = ((const float4*)hidden)[i];
        ((__half2*)g_Xh)[2 * i + 0] = __floats2half2_rn(v.x, v.y);
        ((__half2*)g_Xh)[2 * i + 1] = __floats2half2_rn(v.z, v.w);
    } else if (i < NX4 + NW4) {
        int j = i - NX4;
        float4 v = ((const float4*)W1)[j];
        ((__half2*)g_W1h)[2 * j + 0] = __floats2half2_rn(v.x, v.y);
        ((__half2*)g_W1h)[2 * j + 1] = __floats2half2_rn(v.z, v.w);
    } else if (i < NX4 + 2 * NW4) {
        int j = i - NX4 - NW4;
        float4 v = ((const float4*)W2)[j];
        ((__half2*)g_W2h)[2 * j + 0] = __floats2half2_rn(v.x, v.y);
        ((__half2*)g_W2h)[2 * j + 1] = __floats2half2_rn(v.z, v.w);
    } else {
        int j = i - NX4 - 2 * NW4;
        ((float4*)out)[j] = make_float4(0.f, 0.f, 0.f, 0.f);
    }
}

// ---------------- persistent fp16 grouped gather-GEMM ----------------
// PHASE 1: A = g_Xh[slot>>1] (K=D), B = g_W1h[e] -> g_H[slot] = fp16(gelu(A*B + b1))
// PHASE 2: A = g_H[slot]     (K=F), B = g_W2h[e] -> out[token] += w*(A*B + b2)
template <int PHASE>
__global__ __launch_bounds__(NTHREADS, 2)
void moe_gemm_fp16(const float* __restrict__ bias,
                   const float* __restrict__ wts,
                   float* __restrict__ out) {
    constexpr int KDIM = (PHASE == 1) ? D_DIM : F_DIM;
    constexpr int NDIM = (PHASE == 1) ? F_DIM : D_DIM;
    constexpr int KT   = KDIM / BK;
    constexpr int NT   = NDIM / BN;

    extern __shared__ __align__(1024) char dsm[];
    const uint32_t sbase  = smem_u32(dsm);
    const uint32_t bbase0 = sbase + NSTAGE * A_STAGE_BYTES;

    __shared__ int s_srow[BM];

    const int tid  = threadIdx.x;
    const int wid  = tid >> 5;
    const int lane = tid & 31;
    const int wm = (wid & 1) * 64;
    const int wn = (wid >> 1) * 32;
    const int rA = lane & 15;
    const int cl = lane >> 4;

    // runtime tile enumeration from g_cnt
    int tcnt[E_NUM], tbeg[E_NUM];
    int total_tiles = 0;
    #pragma unroll
    for (int e = 0; e < E_NUM; ++e) {
        tbeg[e] = total_tiles;
        tcnt[e] = g_cnt[e];
        total_tiles += ((tcnt[e] + BM - 1) / BM) * NT;
    }

    for (int tile = blockIdx.x; tile < total_tiles; tile += NCTA) {
        int e = 0;
        #pragma unroll
        for (int q = 1; q < E_NUM; ++q) if (tile >= tbeg[q]) e = q;
        const int local = tile - tbeg[e];
        const int cnt   = tcnt[e];
        const int m0    = (local / NT) * BM;
        const int n0    = (local % NT) * BN;

        const __half* __restrict__ W =
            ((PHASE == 1) ? g_W1h : g_W2h) + (size_t)e * KDIM * NDIM;

        __syncthreads();   // protect s_srow reuse across tiles
        if (tid < BM) s_srow[tid] = g_slots[e][min(m0 + tid, cnt - 1)];
        __syncthreads();

        auto load_stage = [&](int kt) {
            const int s = kt % NSTAGE;
            const uint32_t abuf = sbase + (uint32_t)s * A_STAGE_BYTES;
            const uint32_t bbuf = bbase0 + (uint32_t)s * B_STAGE_BYTES;
            const int k0 = kt * BK;
            #pragma unroll
            for (int it = 0; it < 4; ++it) {           // A: 1024 chunks / 256 thr
                const int c  = tid + it * NTHREADS;
                const int r  = c >> 3;
                const int ch = c & 7;
                const int slot = s_srow[r];
                const __half* asrc = (PHASE == 1)
                    ? g_Xh + (size_t)(slot >> 1) * D_DIM + k0 + ch * 8
                    : g_H  + (size_t)slot * F_DIM        + k0 + ch * 8;
                cp_async16(abuf + (uint32_t)(r * 128 + ((ch ^ (r & 7)) << 4)), asrc);
            }
            #pragma unroll
            for (int it = 0; it < 4; ++it) {           // B: 64 rows x 16 chunks
                const int c  = tid + it * NTHREADS;
                const int r  = c >> 4;
                const int ch = c & 15;
                const __half* bsrc = W + (size_t)(k0 + r) * NDIM + n0 + ch * 8;
                cp_async16(bbuf + (uint32_t)(r * 256 + ((ch ^ (r & 7)) << 4)), bsrc);
            }
            cp_commit();
        };

        float acc[4][4][4];
        #pragma unroll
        for (int i = 0; i < 4; ++i)
            #pragma unroll
            for (int j = 0; j < 4; ++j)
                #pragma unroll
                for (int r = 0; r < 4; ++r) acc[i][j][r] = 0.f;

        load_stage(0);
        load_stage(1);

        for (int kt = 0; kt < KT; ++kt) {
            if (kt + 2 < KT) load_stage(kt + 2);
            if (kt + 2 < KT)      { cp_wait<2>(); }
            else if (kt + 1 < KT) { cp_wait<1>(); }
            else                  { cp_wait<0>(); }
            __syncthreads();

            const int s = kt % NSTAGE;
            const uint32_t abuf = sbase + (uint32_t)s * A_STAGE_BYTES;
            const uint32_t bbuf = bbase0 + (uint32_t)s * B_STAGE_BYTES;

            #pragma unroll
            for (int ks = 0; ks < BK / 16; ++ks) {
                uint32_t af[4][4];
                #pragma unroll
                for (int mf = 0; mf < 4; ++mf) {
                    const int r = wm + mf * 16 + rA;
                    const int chA = ks * 2 + cl;
                    ldsm_x4(af[mf], abuf + (uint32_t)(r * 128 + ((chA ^ (r & 7)) << 4)));
                }
                uint32_t bf[2][4];
                #pragma unroll
                for (int nf16 = 0; nf16 < 2; ++nf16) {
                    const int r = ks * 16 + rA;
                    const int chB = (wn >> 3) + nf16 * 2 + cl;
                    ldsm_x4_trans(bf[nf16], bbuf + (uint32_t)(r * 256 + ((chB ^ (r & 7)) << 4)));
                }
                #pragma unroll
                for (int mf = 0; mf < 4; ++mf)
                    #pragma unroll
                    for (int nf = 0; nf < 4; ++nf) {
                        const int g = nf >> 1;
                        const int h = (nf & 1) * 2;
                        mma_fp16(acc[mf][nf], af[mf], bf[g][h], bf[g][h + 1]);
                    }
            }
            __syncthreads();
        }

        // ---------------- epilogue ----------------
        const int rbase = wm + (lane >> 2);
        const int cbase = wn + 2 * (lane & 3);
        const float* __restrict__ brow = bias + (size_t)e * NDIM + n0;
        #pragma unroll
        for (int mf = 0; mf < 4; ++mf) {
            #pragma unroll
            for (int half = 0; half < 2; ++half) {
                const int rloc = rbase + mf * 16 + half * 8;
                const int gm   = m0 + rloc;
                if (gm < cnt) {
                    const int slot = s_srow[rloc];
                    if (PHASE == 1) {
                        __half* __restrict__ orow = g_H + (size_t)slot * F_DIM + n0;
                        #pragma unroll
                        for (int nf = 0; nf < 4; ++nf) {
                            const int col = cbase + nf * 8;
                            const float2 bv = *(const float2*)(brow + col);
                            float v0 = gelu_tanh(acc[mf][nf][half * 2 + 0] + bv.x);
                            float v1 = gelu_tanh(acc[mf][nf][half * 2 + 1] + bv.y);
                            *(__half2*)(orow + col) = __floats2half2_rn(v0, v1);
                        }
                    } else {
                        const float w = __ldg(wts + slot);
                        float* __restrict__ orow = out + (size_t)(slot >> 1) * D_DIM + n0;
                        #pragma unroll
                        for (int nf = 0; nf < 4; ++nf) {
                            const int col = cbase + nf * 8;
                            const float2 bv = *(const float2*)(brow + col);
                            float v0 = (acc[mf][nf][half * 2 + 0] + bv.x) * w;
                            float v1 = (acc[mf][nf][half * 2 + 1] + bv.y) * w;
                            red_add_v2(orow + col, v0, v1);
                        }
                    }
                }
            }
        }
    }
}

// ---------------- launch ----------------
extern "C" void kernel_launch(void* const* d_in, const int* in_sizes, int n_in,
                              void* d_out, int out_size) {
    const float* hidden = (const float*)d_in[0];
    const int*   idx    = (const int*)d_in[1];
    const float* wts    = (const float*)d_in[2];
    const float* W1     = (const float*)d_in[3];
    const float* b1     = (const float*)d_in[4];
    const float* W2     = (const float*)d_in[5];
    const float* b2     = (const float*)d_in[6];
    float*       out    = (float*)d_out;
    (void)in_sizes; (void)n_in; (void)out_size;

    cudaFuncSetAttribute(moe_gemm_fp16<1>, cudaFuncAttributeMaxDynamicSharedMemorySize, SMEM_BYTES);
    cudaFuncSetAttribute(moe_gemm_fp16<2>, cudaFuncAttributeMaxDynamicSharedMemorySize, SMEM_BYTES);

    zero_counts_kernel<<<1, 32>>>();
    route_kernel<<<NSLOT / 256, 256>>>(idx);

    const int prep_total = NX4 + 2 * NW4 + NX4;
    prep_kernel<<<(prep_total + 255) / 256, 256>>>(hidden, W1, W2, out);

    moe_gemm_fp16<1><<<NCTA, NTHREADS, SMEM_BYTES>>>(b1, nullptr, nullptr);
    moe_gemm_fp16<2><<<NCTA, NTHREADS, SMEM_BYTES>>>(b2, wts, out);
}

// round 6
// speedup vs baseline: 1.8840x; 1.0378x over previous
#include <cuda_runtime.h>
#include <cuda_fp16.h>
#include <cstdint>

// ---------------- problem constants ----------------
#define T_TOK 8192
#define D_DIM 512
#define F_DIM 1024
#define E_NUM 8
#define K_TOP 2
#define NSLOT (T_TOK * K_TOP)      // 16384 slots

// ---------------- GEMM tiling ----------------
#define BM 128
#define BN 128
#define BK 64                       // 64 fp16 = 128B A-rows, B rows 256B
#define NSTAGE 3
#define NTHREADS 256                // 8 warps: 2(m) x 4(n) of 64x32
#define NCTA 296                    // persistent grid, 2 CTAs/SM
#define A_STAGE_BYTES (BM * 128)    // 16 KB
#define B_STAGE_BYTES (BK * 256)    // 16 KB
#define SMEM_BYTES (NSTAGE * (A_STAGE_BYTES + B_STAGE_BYTES))   // 96 KB

// ---------------- device scratch (no cudaMalloc allowed) ----------------
__device__ int    g_slots[E_NUM][NSLOT];
__device__ int    g_cnt[E_NUM];
__device__ __half g_Xh[(size_t)T_TOK * D_DIM];              // 8 MB
__device__ __half g_H[(size_t)NSLOT * F_DIM];               // 32 MB
__device__ __half g_W1h[(size_t)E_NUM * D_DIM * F_DIM];     // 8 MB [E][D][F]
__device__ __half g_W2h[(size_t)E_NUM * F_DIM * D_DIM];     // 8 MB [E][F][D]

// ---------------- PTX helpers ----------------
__device__ __forceinline__ uint32_t smem_u32(const void* p) {
    uint32_t a;
    asm("{ .reg .u64 t; cvta.to.shared.u64 t, %1; cvt.u32.u64 %0, t; }" : "=r"(a) : "l"(p));
    return a;
}
__device__ __forceinline__ void cp_async16(uint32_t dst, const void* src) {
    asm volatile("cp.async.cg.shared.global [%0], [%1], 16;\n" :: "r"(dst), "l"(src));
}
__device__ __forceinline__ void cp_commit() { asm volatile("cp.async.commit_group;\n"); }
template <int N>
__device__ __forceinline__ void cp_wait() {
    asm volatile("cp.async.wait_group %0;\n" :: "n"(N) : "memory");
}
__device__ __forceinline__ void ldsm_x4(uint32_t* r, uint32_t addr) {
    asm volatile("ldmatrix.sync.aligned.m8n8.x4.shared.b16 {%0,%1,%2,%3}, [%4];"
                 : "=r"(r[0]), "=r"(r[1]), "=r"(r[2]), "=r"(r[3]) : "r"(addr));
}
__device__ __forceinline__ void ldsm_x4_trans(uint32_t* r, uint32_t addr) {
    asm volatile("ldmatrix.sync.aligned.m8n8.x4.trans.shared.b16 {%0,%1,%2,%3}, [%4];"
                 : "=r"(r[0]), "=r"(r[1]), "=r"(r[2]), "=r"(r[3]) : "r"(addr));
}
__device__ __forceinline__ void mma_fp16(float c[4], const uint32_t a[4],
                                         uint32_t b0, uint32_t b1) {
    asm volatile(
        "mma.sync.aligned.m16n8k16.row.col.f32.f16.f16.f32 "
        "{%0,%1,%2,%3},{%4,%5,%6,%7},{%8,%9},{%0,%1,%2,%3};\n"
        : "+f"(c[0]), "+f"(c[1]), "+f"(c[2]), "+f"(c[3])
        : "r"(a[0]), "r"(a[1]), "r"(a[2]), "r"(a[3]), "r"(b0), "r"(b1));
}
__device__ __forceinline__ void red_add_v2(float* p, float v0, float v1) {
    asm volatile("red.relaxed.gpu.global.add.v2.f32 [%0], {%1,%2};"
                 :: "l"(p), "f"(v0), "f"(v1) : "memory");
}

__device__ __forceinline__ float gelu_tanh(float x) {
    float x3 = x * x * x;
    float t = tanhf(0.7978845608028654f * (x + 0.044715f * x3));
    return 0.5f * x * (1.0f + t);
}

// ---------------- routing / setup ----------------
__global__ void zero_counts_kernel() {
    if (threadIdx.x < E_NUM) g_cnt[threadIdx.x] = 0;
}
__global__ void route_kernel(const int* __restrict__ idx) {
    int s = blockIdx.x * blockDim.x + threadIdx.x;
    if (s < NSLOT) {
        int e = idx[s];
        int p = atomicAdd(&g_cnt[e], 1);
        g_slots[e][p] = s;
    }
}
// fused prep: convert hidden/W1/W2 to fp16 and zero the output
#define NX4 (T_TOK * D_DIM / 4)
#define NW4 (E_NUM * D_DIM * F_DIM / 4)
__global__ void prep_kernel(const float* __restrict__ hidden,
                            const float* __restrict__ W1,
                            const float* __restrict__ W2,
                            float* __restrict__ out) {
    const int i = blockIdx.x * blockDim.x + threadIdx.x;
    const int total = NX4 + 2 * NW4 + NX4;
    if (i >= total) return;
    if (i < NX4) {
        float4 v = ((const float4*)hidden)[i];
        ((__half2*)g_Xh)[2 * i + 0] = __floats2half2_rn(v.x, v.y);
        ((__half2*)g_Xh)[2 * i + 1] = __floats2half2_rn(v.z, v.w);
    } else if (i < NX4 + NW4) {
        int j = i - NX4;
        float4 v = ((const float4*)W1)[j];
        ((__half2*)g_W1h)[2 * j + 0] = __floats2half2_rn(v.x, v.y);
        ((__half2*)g_W1h)[2 * j + 1] = __floats2half2_rn(v.z, v.w);
    } else if (i < NX4 + 2 * NW4) {
        int j = i - NX4 - NW4;
        float4 v = ((const float4*)W2)[j];
        ((__half2*)g_W2h)[2 * j + 0] = __floats2half2_rn(v.x, v.y);
        ((__half2*)g_W2h)[2 * j + 1] = __floats2half2_rn(v.z, v.w);
    } else {
        int j = i - NX4 - 2 * NW4;
        ((float4*)out)[j] = make_float4(0.f, 0.f, 0.f, 0.f);
    }
}

// ---------------- persistent fp16 grouped gather-GEMM ----------------
// PHASE 1: A = g_Xh[slot>>1] (K=D), B = g_W1h[e] -> g_H[slot] = fp16(gelu(A*B + b1))
// PHASE 2: A = g_H[slot]     (K=F), B = g_W2h[e] -> out[token] += w*(A*B + b2)
template <int PHASE>
__global__ __launch_bounds__(NTHREADS, 2)
void moe_gemm_fp16(const float* __restrict__ bias,
                   const float* __restrict__ wts,
                   float* __restrict__ out) {
    constexpr int KDIM = (PHASE == 1) ? D_DIM : F_DIM;
    constexpr int NDIM = (PHASE == 1) ? F_DIM : D_DIM;
    constexpr int KT   = KDIM / BK;
    constexpr int NT   = NDIM / BN;

    extern __shared__ __align__(1024) char dsm[];
    const uint32_t sbase  = smem_u32(dsm);
    const uint32_t bbase0 = sbase + NSTAGE * A_STAGE_BYTES;

    __shared__ int s_srow[BM];

    const int tid  = threadIdx.x;
    const int wid  = tid >> 5;
    const int lane = tid & 31;
    const int wm = (wid & 1) * 64;
    const int wn = (wid >> 1) * 32;
    const int rA = lane & 15;
    const int cl = lane >> 4;

    // loop-invariant LDSM fragment offsets (per warp/lane)
    uint32_t offA[4][4], offB[4][2];
    #pragma unroll
    for (int mf = 0; mf < 4; ++mf) {
        const int r = wm + mf * 16 + rA;
        #pragma unroll
        for (int ks = 0; ks < 4; ++ks)
            offA[mf][ks] = (uint32_t)(r * 128 + (((ks * 2 + cl) ^ (r & 7)) << 4));
    }
    #pragma unroll
    for (int ks = 0; ks < 4; ++ks) {
        const int rb = ks * 16 + rA;
        #pragma unroll
        for (int nf16 = 0; nf16 < 2; ++nf16)
            offB[ks][nf16] = (uint32_t)(rb * 256 +
                              ((((wn >> 3) + nf16 * 2 + cl) ^ (rb & 7)) << 4));
    }

    // runtime tile enumeration from g_cnt
    int tcnt[E_NUM], tbeg[E_NUM];
    int total_tiles = 0;
    #pragma unroll
    for (int e = 0; e < E_NUM; ++e) {
        tbeg[e] = total_tiles;
        tcnt[e] = g_cnt[e];
        total_tiles += ((tcnt[e] + BM - 1) / BM) * NT;
    }

    for (int tile = blockIdx.x; tile < total_tiles; tile += NCTA) {
        int e = 0;
        #pragma unroll
        for (int q = 1; q < E_NUM; ++q) if (tile >= tbeg[q]) e = q;
        const int local = tile - tbeg[e];
        const int cnt   = tcnt[e];
        const int m0    = (local / NT) * BM;
        const int n0    = (local % NT) * BN;

        const __half* __restrict__ W =
            ((PHASE == 1) ? g_W1h : g_W2h) + (size_t)e * KDIM * NDIM;

        __syncthreads();   // all warps done with previous tile (epilogue + smem reads)
        if (tid < BM) s_srow[tid] = g_slots[e][min(m0 + tid, cnt - 1)];
        __syncthreads();

        auto load_stage = [&](int kt) {
            const int s = kt % NSTAGE;
            const uint32_t abuf = sbase + (uint32_t)s * A_STAGE_BYTES;
            const uint32_t bbuf = bbase0 + (uint32_t)s * B_STAGE_BYTES;
            const int k0 = kt * BK;
            #pragma unroll
            for (int it = 0; it < 4; ++it) {           // A: 1024 chunks / 256 thr
                const int c  = tid + it * NTHREADS;
                const int r  = c >> 3;
                const int ch = c & 7;
                const int slot = s_srow[r];
                const __half* asrc = (PHASE == 1)
                    ? g_Xh + (size_t)(slot >> 1) * D_DIM + k0 + ch * 8
                    : g_H  + (size_t)slot * F_DIM        + k0 + ch * 8;
                cp_async16(abuf + (uint32_t)(r * 128 + ((ch ^ (r & 7)) << 4)), asrc);
            }
            #pragma unroll
            for (int it = 0; it < 4; ++it) {           // B: 64 rows x 16 chunks
                const int c  = tid + it * NTHREADS;
                const int r  = c >> 4;
                const int ch = c & 15;
                const __half* bsrc = W + (size_t)(k0 + r) * NDIM + n0 + ch * 8;
                cp_async16(bbuf + (uint32_t)(r * 256 + ((ch ^ (r & 7)) << 4)), bsrc);
            }
            cp_commit();
        };

        float acc[4][4][4];
        #pragma unroll
        for (int i = 0; i < 4; ++i)
            #pragma unroll
            for (int j = 0; j < 4; ++j)
                #pragma unroll
                for (int r = 0; r < 4; ++r) acc[i][j][r] = 0.f;

        load_stage(0);
        load_stage(1);

        for (int kt = 0; kt < KT; ++kt) {
            if (kt + 1 < KT) { cp_wait<1>(); } else { cp_wait<0>(); }
            __syncthreads();           // single barrier per k-iteration

            const int s = kt % NSTAGE;
            const uint32_t abuf = sbase + (uint32_t)s * A_STAGE_BYTES;
            const uint32_t bbuf = bbase0 + (uint32_t)s * B_STAGE_BYTES;

            #pragma unroll
            for (int ks = 0; ks < BK / 16; ++ks) {
                uint32_t af[4][4];
                #pragma unroll
                for (int mf = 0; mf < 4; ++mf)
                    ldsm_x4(af[mf], abuf + offA[mf][ks]);
                uint32_t bf[2][4];
                #pragma unroll
                for (int nf16 = 0; nf16 < 2; ++nf16)
                    ldsm_x4_trans(bf[nf16], bbuf + offB[ks][nf16]);
                #pragma unroll
                for (int mf = 0; mf < 4; ++mf)
                    #pragma unroll
                    for (int nf = 0; nf < 4; ++nf) {
                        const int g = nf >> 1;
                        const int h = (nf & 1) * 2;
                        mma_fp16(acc[mf][nf], af[mf], bf[g][h], bf[g][h + 1]);
                    }
            }

            // safe: writes buffer (kt+2)%3 == (kt-1)%3, fully consumed before
            // the barrier at the top of this iteration
            if (kt + 2 < KT) load_stage(kt + 2);
        }

        // ---------------- epilogue ----------------
        const int rbase = wm + (lane >> 2);
        const int cbase = wn + 2 * (lane & 3);
        const float* __restrict__ brow = bias + (size_t)e * NDIM + n0;
        #pragma unroll
        for (int mf = 0; mf < 4; ++mf) {
            #pragma unroll
            for (int half = 0; half < 2; ++half) {
                const int rloc = rbase + mf * 16 + half * 8;
                const int gm   = m0 + rloc;
                if (gm < cnt) {
                    const int slot = s_srow[rloc];
                    if (PHASE == 1) {
                        __half* __restrict__ orow = g_H + (size_t)slot * F_DIM + n0;
                        #pragma unroll
                        for (int nf = 0; nf < 4; ++nf) {
                            const int col = cbase + nf * 8;
                            const float2 bv = *(const float2*)(brow + col);
                            float v0 = gelu_tanh(acc[mf][nf][half * 2 + 0] + bv.x);
                            float v1 = gelu_tanh(acc[mf][nf][half * 2 + 1] + bv.y);
                            *(__half2*)(orow + col) = __floats2half2_rn(v0, v1);
                        }
                    } else {
                        const float w = __ldg(wts + slot);
                        float* __restrict__ orow = out + (size_t)(slot >> 1) * D_DIM + n0;
                        #pragma unroll
                        for (int nf = 0; nf < 4; ++nf) {
                            const int col = cbase + nf * 8;
                            const float2 bv = *(const float2*)(brow + col);
                            float v0 = (acc[mf][nf][half * 2 + 0] + bv.x) * w;
                            float v1 = (acc[mf][nf][half * 2 + 1] + bv.y) * w;
                            red_add_v2(orow + col, v0, v1);
                        }
                    }
                }
            }
        }
    }
}

// ---------------- launch ----------------
extern "C" void kernel_launch(void* const* d_in, const int* in_sizes, int n_in,
                              void* d_out, int out_size) {
    const float* hidden = (const float*)d_in[0];
    const int*   idx    = (const int*)d_in[1];
    const float* wts    = (const float*)d_in[2];
    const float* W1     = (const float*)d_in[3];
    const float* b1     = (const float*)d_in[4];
    const float* W2     = (const float*)d_in[5];
    const float* b2     = (const float*)d_in[6];
    float*       out    = (float*)d_out;
    (void)in_sizes; (void)n_in; (void)out_size;

    cudaFuncSetAttribute(moe_gemm_fp16<1>, cudaFuncAttributeMaxDynamicSharedMemorySize, SMEM_BYTES);
    cudaFuncSetAttribute(moe_gemm_fp16<2>, cudaFuncAttributeMaxDynamicSharedMemorySize, SMEM_BYTES);

    zero_counts_kernel<<<1, 32>>>();
    route_kernel<<<NSLOT / 256, 256>>>(idx);

    const int prep_total = NX4 + 2 * NW4 + NX4;
    prep_kernel<<<(prep_total + 255) / 256, 256>>>(hidden, W1, W2, out);

    moe_gemm_fp16<1><<<NCTA, NTHREADS, SMEM_BYTES>>>(b1, nullptr, nullptr);
    moe_gemm_fp16<2><<<NCTA, NTHREADS, SMEM_BYTES>>>(b2, wts, out);
}

// round 7
// speedup vs baseline: 1.9609x; 1.0409x over previous
#include <cuda_runtime.h>
#include <cuda_fp16.h>
#include <cstdint>

// ---------------- problem constants ----------------
#define T_TOK 8192
#define D_DIM 512
#define F_DIM 1024
#define E_NUM 8
#define K_TOP 2
#define NSLOT (T_TOK * K_TOP)      // 16384 slots

// ---------------- GEMM tiling ----------------
#define BM 128
#define BN 128
#define BK 64
#define NSTAGE 3
#define NTHREADS 256                // 8 warps: 2(m) x 4(n) of 64x32
#define NCTA 296                    // persistent grid, 2 CTAs/SM
#define A_STAGE_BYTES (BM * 128)    // 16 KB
#define B_STAGE_BYTES (BK * 256)    // 16 KB (64 k-rows x 128 halves, pre-swizzled)
#define SMEM_BYTES (NSTAGE * (A_STAGE_BYTES + B_STAGE_BYTES))   // 96 KB

// ---------------- device scratch (no cudaMalloc allowed) ----------------
__device__ int    g_slots[E_NUM][NSLOT];
__device__ int    g_cnt[E_NUM];
__device__ __half g_Xh[(size_t)T_TOK * D_DIM];              // 8 MB
__device__ __half g_H[(size_t)NSLOT * F_DIM];               // 32 MB
// packed + pre-swizzled weight tiles: [e][ntile][k] rows of 128 halves (256B)
__device__ __half g_W1p[(size_t)E_NUM * D_DIM * F_DIM];     // 8 MB
__device__ __half g_W2p[(size_t)E_NUM * F_DIM * D_DIM];     // 8 MB

// ---------------- PTX helpers ----------------
__device__ __forceinline__ uint32_t smem_u32(const void* p) {
    uint32_t a;
    asm("{ .reg .u64 t; cvta.to.shared.u64 t, %1; cvt.u32.u64 %0, t; }" : "=r"(a) : "l"(p));
    return a;
}
__device__ __forceinline__ void cp_async16(uint32_t dst, const void* src) {
    asm volatile("cp.async.cg.shared.global [%0], [%1], 16;\n" :: "r"(dst), "l"(src));
}
__device__ __forceinline__ void cp_commit() { asm volatile("cp.async.commit_group;\n"); }
template <int N>
__device__ __forceinline__ void cp_wait() {
    asm volatile("cp.async.wait_group %0;\n" :: "n"(N) : "memory");
}
__device__ __forceinline__ void cp_bulk(uint32_t dst, const void* src,
                                        uint32_t bytes, uint32_t mbar) {
    asm volatile("cp.async.bulk.shared::cta.global.mbarrier::complete_tx::bytes "
                 "[%0], [%1], %2, [%3];"
                 :: "r"(dst), "l"(src), "r"(bytes), "r"(mbar) : "memory");
}
__device__ __forceinline__ void mbar_init(uint32_t addr, uint32_t cnt) {
    asm volatile("mbarrier.init.shared.b64 [%0], %1;" :: "r"(addr), "r"(cnt) : "memory");
}
__device__ __forceinline__ void mbar_expect_tx(uint32_t addr, uint32_t bytes) {
    asm volatile("mbarrier.arrive.expect_tx.shared.b64 _, [%0], %1;"
                 :: "r"(addr), "r"(bytes) : "memory");
}
__device__ __forceinline__ void mbar_wait(uint32_t addr, uint32_t phase) {
    asm volatile(
        "{\n\t.reg .pred P;\n"
        "W%=:\n\t"
        "mbarrier.try_wait.parity.shared::cta.b64 P, [%0], %1, 0x989680;\n\t"
        "@!P bra W%=;\n"
        "}" :: "r"(addr), "r"(phase) : "memory");
}
__device__ __forceinline__ void ldsm_x4(uint32_t* r, uint32_t addr) {
    asm volatile("ldmatrix.sync.aligned.m8n8.x4.shared.b16 {%0,%1,%2,%3}, [%4];"
                 : "=r"(r[0]), "=r"(r[1]), "=r"(r[2]), "=r"(r[3]) : "r"(addr));
}
__device__ __forceinline__ void ldsm_x4_trans(uint32_t* r, uint32_t addr) {
    asm volatile("ldmatrix.sync.aligned.m8n8.x4.trans.shared.b16 {%0,%1,%2,%3}, [%4];"
                 : "=r"(r[0]), "=r"(r[1]), "=r"(r[2]), "=r"(r[3]) : "r"(addr));
}
__device__ __forceinline__ void mma_fp16(float c[4], const uint32_t a[4],
                                         uint32_t b0, uint32_t b1) {
    asm volatile(
        "mma.sync.aligned.m16n8k16.row.col.f32.f16.f16.f32 "
        "{%0,%1,%2,%3},{%4,%5,%6,%7},{%8,%9},{%0,%1,%2,%3};\n"
        : "+f"(c[0]), "+f"(c[1]), "+f"(c[2]), "+f"(c[3])
        : "r"(a[0]), "r"(a[1]), "r"(a[2]), "r"(a[3]), "r"(b0), "r"(b1));
}
__device__ __forceinline__ void red_add_v2(float* p, float v0, float v1) {
    asm volatile("red.relaxed.gpu.global.add.v2.f32 [%0], {%1,%2};"
                 :: "l"(p), "f"(v0), "f"(v1) : "memory");
}
__device__ __forceinline__ uint32_t f22h2(float a, float b) {
    __half2 h = __floats2half2_rn(a, b);
    return *reinterpret_cast<uint32_t*>(&h);
}

// tanh-approx gelu: gelu(x) = x*E/(E+1), E = exp(2z), z = 0.79788456(x + 0.044715 x^3)
// exact same formula as jax tanh gelu; ex2/rcp approx err ~1e-6. Saturation handled
// naturally (E=inf -> x; E=0 -> 0).
__device__ __forceinline__ float gelu_fast(float x) {
    float z = 0.7978845608028654f * fmaf(0.044715f * x, x * x, x);
    float E;
    asm("ex2.approx.f32 %0, %1;" : "=f"(E) : "f"(z * 2.8853900817779268f));
    float r;
    asm("rcp.approx.f32 %0, %1;" : "=f"(r) : "f"(E + 1.0f));
    return x - x * r;
}

// ---------------- routing / setup ----------------
__global__ void zero_counts_kernel() {
    if (threadIdx.x < E_NUM) g_cnt[threadIdx.x] = 0;
}
__global__ void route_kernel(const int* __restrict__ idx) {
    int s = blockIdx.x * blockDim.x + threadIdx.x;
    if (s < NSLOT) {
        int e = idx[s];
        int p = atomicAdd(&g_cnt[e], 1);
        g_slots[e][p] = s;
    }
}

// fused prep:
//  - hidden fp32 -> fp16 (row-major)
//  - W1/W2 fp32 -> fp16 packed per (expert, n-tile), K-major 256B rows,
//    XOR-swizzle baked in: dst chunk p of row k holds source n-chunk p^(k&7)
//  - zero output
#define NX4 (T_TOK * D_DIM / 4)                 // 1,048,576
#define NWC (E_NUM * D_DIM * F_DIM / 8)         // 524,288 16B-chunks per weight
__global__ void prep_kernel(const float* __restrict__ hidden,
                            const float* __restrict__ W1,
                            const float* __restrict__ W2,
                            float* __restrict__ out) {
    const int i = blockIdx.x * blockDim.x + threadIdx.x;
    const int total = NX4 + 2 * NWC + NX4;
    if (i >= total) return;
    if (i < NX4) {
        float4 v = ((const float4*)hidden)[i];
        ((__half2*)g_Xh)[2 * i + 0] = __floats2half2_rn(v.x, v.y);
        ((__half2*)g_Xh)[2 * i + 1] = __floats2half2_rn(v.z, v.w);
    } else if (i < NX4 + NWC) {
        // W1: KDIM=512, NT=8
        const int j  = i - NX4;
        const int e  = j >> 16;            // 65536 chunks / expert
        const int c  = j & 0xFFFF;
        const int nt = c >> 13;            // 512*16 = 8192 chunks / n-tile
        const int k  = (c >> 4) & 511;
        const int p  = c & 15;
        const int ch = p ^ (k & 7);
        const float* s = W1 + ((size_t)(e * 512 + k)) * F_DIM + nt * 128 + ch * 8;
        float4 v0 = *(const float4*)s, v1 = *(const float4*)(s + 4);
        uint4 o;
        o.x = f22h2(v0.x, v0.y); o.y = f22h2(v0.z, v0.w);
        o.z = f22h2(v1.x, v1.y); o.w = f22h2(v1.z, v1.w);
        *(uint4*)(g_W1p + ((size_t)((e * 8 + nt) * 512 + k)) * 128 + p * 8) = o;
    } else if (i < NX4 + 2 * NWC) {
        // W2: KDIM=1024, NT=4
        const int j  = i - NX4 - NWC;
        const int e  = j >> 16;
        const int c  = j & 0xFFFF;
        const int nt = c >> 14;            // 1024*16 = 16384 chunks / n-tile
        const int k  = (c >> 4) & 1023;
        const int p  = c & 15;
        const int ch = p ^ (k & 7);
        const float* s = W2 + ((size_t)(e * 1024 + k)) * D_DIM + nt * 128 + ch * 8;
        float4 v0 = *(const float4*)s, v1 = *(const float4*)(s + 4);
        uint4 o;
        o.x = f22h2(v0.x, v0.y); o.y = f22h2(v0.z, v0.w);
        o.z = f22h2(v1.x, v1.y); o.w = f22h2(v1.z, v1.w);
        *(uint4*)(g_W2p + ((size_t)((e * 4 + nt) * 1024 + k)) * 128 + p * 8) = o;
    } else {
        int j = i - NX4 - 2 * NWC;
        ((float4*)out)[j] = make_float4(0.f, 0.f, 0.f, 0.f);
    }
}

// ---------------- persistent fp16 grouped gather-GEMM ----------------
// PHASE 1: A = g_Xh[slot>>1] (K=D), B = g_W1p -> g_H[slot] = fp16(gelu(A*B + b1))
// PHASE 2: A = g_H[slot]     (K=F), B = g_W2p -> out[token] += w*(A*B + b2)
template <int PHASE>
__global__ __launch_bounds__(NTHREADS, 2)
void moe_gemm_fp16(const float* __restrict__ bias,
                   const float* __restrict__ wts,
                   float* __restrict__ out) {
    constexpr int KDIM = (PHASE == 1) ? D_DIM : F_DIM;
    constexpr int NDIM = (PHASE == 1) ? F_DIM : D_DIM;
    constexpr int KT   = KDIM / BK;
    constexpr int NT   = NDIM / BN;

    extern __shared__ __align__(1024) char dsm[];
    const uint32_t sbase  = smem_u32(dsm);
    const uint32_t bbase0 = sbase + NSTAGE * A_STAGE_BYTES;

    __shared__ int      s_srow[BM];
    __shared__ uint64_t s_mbar[NSTAGE];

    const int tid  = threadIdx.x;
    const int wid  = tid >> 5;
    const int lane = tid & 31;
    const int wm = (wid & 1) * 64;
    const int wn = (wid >> 1) * 32;
    const int rA = lane & 15;
    const int cl = lane >> 4;

    if (tid == 0) {
        #pragma unroll
        for (int s = 0; s < NSTAGE; ++s) mbar_init(smem_u32(&s_mbar[s]), 1);
    }
    __syncthreads();
    int ph[NSTAGE];
    #pragma unroll
    for (int s = 0; s < NSTAGE; ++s) ph[s] = 0;

    // loop-invariant LDSM fragment offsets
    uint32_t offA[4][4], offB[4][2];
    #pragma unroll
    for (int mf = 0; mf < 4; ++mf) {
        const int r = wm + mf * 16 + rA;
        #pragma unroll
        for (int ks = 0; ks < 4; ++ks)
            offA[mf][ks] = (uint32_t)(r * 128 + (((ks * 2 + cl) ^ (r & 7)) << 4));
    }
    #pragma unroll
    for (int ks = 0; ks < 4; ++ks) {
        const int rb = ks * 16 + rA;
        #pragma unroll
        for (int nf16 = 0; nf16 < 2; ++nf16)
            offB[ks][nf16] = (uint32_t)(rb * 256 +
                              ((((wn >> 3) + nf16 * 2 + cl) ^ (rb & 7)) << 4));
    }

    // runtime tile enumeration from g_cnt
    int tcnt[E_NUM], tbeg[E_NUM];
    int total_tiles = 0;
    #pragma unroll
    for (int e = 0; e < E_NUM; ++e) {
        tbeg[e] = total_tiles;
        tcnt[e] = g_cnt[e];
        total_tiles += ((tcnt[e] + BM - 1) / BM) * NT;
    }

    for (int tile = blockIdx.x; tile < total_tiles; tile += NCTA) {
        int e = 0;
        #pragma unroll
        for (int q = 1; q < E_NUM; ++q) if (tile >= tbeg[q]) e = q;
        const int local = tile - tbeg[e];
        const int cnt   = tcnt[e];
        const int m0    = (local / NT) * BM;
        const int nt    = local % NT;
        const int n0    = nt * BN;

        // packed B tile base for this (expert, n-tile)
        const __half* __restrict__ Wtile =
            ((PHASE == 1) ? g_W1p : g_W2p) + (size_t)(e * NT + nt) * KDIM * 128;

        __syncthreads();   // all warps done with previous tile
        if (tid < BM) s_srow[tid] = g_slots[e][min(m0 + tid, cnt - 1)];
        __syncthreads();

        auto load_stage = [&](int kt) {
            const int s = kt % NSTAGE;
            const uint32_t abuf = sbase + (uint32_t)s * A_STAGE_BYTES;
            const int k0 = kt * BK;
            #pragma unroll
            for (int it = 0; it < 4; ++it) {           // A: 1024 chunks / 256 thr
                const int c  = tid + it * NTHREADS;
                const int r  = c >> 3;
                const int ch = c & 7;
                const int slot = s_srow[r];
                const __half* asrc = (PHASE == 1)
                    ? g_Xh + (size_t)(slot >> 1) * D_DIM + k0 + ch * 8
                    : g_H  + (size_t)slot * F_DIM        + k0 + ch * 8;
                cp_async16(abuf + (uint32_t)(r * 128 + ((ch ^ (r & 7)) << 4)), asrc);
            }
            cp_commit();
            if (tid == 0) {                            // B: one 16KB bulk copy
                const uint32_t mb = smem_u32(&s_mbar[s]);
                mbar_expect_tx(mb, B_STAGE_BYTES);
                cp_bulk(bbase0 + (uint32_t)s * B_STAGE_BYTES,
                        Wtile + (size_t)k0 * 128, B_STAGE_BYTES, mb);
            }
        };

        float acc[4][4][4];
        #pragma unroll
        for (int i = 0; i < 4; ++i)
            #pragma unroll
            for (int j = 0; j < 4; ++j)
                #pragma unroll
                for (int r = 0; r < 4; ++r) acc[i][j][r] = 0.f;

        load_stage(0);
        load_stage(1);

        for (int kt = 0; kt < KT; ++kt) {
            const int s = kt % NSTAGE;
            if (kt + 1 < KT) { cp_wait<1>(); } else { cp_wait<0>(); }
            mbar_wait(smem_u32(&s_mbar[s]), ph[s]);
            ph[s] ^= 1;
            __syncthreads();           // single barrier per k-iteration

            const uint32_t abuf = sbase + (uint32_t)s * A_STAGE_BYTES;
            const uint32_t bbuf = bbase0 + (uint32_t)s * B_STAGE_BYTES;

            #pragma unroll
            for (int ks = 0; ks < BK / 16; ++ks) {
                uint32_t af[4][4];
                #pragma unroll
                for (int mf = 0; mf < 4; ++mf)
                    ldsm_x4(af[mf], abuf + offA[mf][ks]);
                uint32_t bf[2][4];
                #pragma unroll
                for (int nf16 = 0; nf16 < 2; ++nf16)
                    ldsm_x4_trans(bf[nf16], bbuf + offB[ks][nf16]);
                #pragma unroll
                for (int mf = 0; mf < 4; ++mf)
                    #pragma unroll
                    for (int nf = 0; nf < 4; ++nf) {
                        const int g = nf >> 1;
                        const int h = (nf & 1) * 2;
                        mma_fp16(acc[mf][nf], af[mf], bf[g][h], bf[g][h + 1]);
                    }
            }

            // writes buffer (kt+2)%3 == (kt-1)%3, fully consumed before the
            // barrier at the top of this iteration
            if (kt + 2 < KT) load_stage(kt + 2);
        }

        // ---------------- epilogue ----------------
        const int rbase = wm + (lane >> 2);
        const int cbase = wn + 2 * (lane & 3);
        const float* __restrict__ brow = bias + (size_t)e * NDIM + n0;
        #pragma unroll
        for (int mf = 0; mf < 4; ++mf) {
            #pragma unroll
            for (int half = 0; half < 2; ++half) {
                const int rloc = rbase + mf * 16 + half * 8;
                const int gm   = m0 + rloc;
                if (gm < cnt) {
                    const int slot = s_srow[rloc];
                    if (PHASE == 1) {
                        __half* __restrict__ orow = g_H + (size_t)slot * F_DIM + n0;
                        #pragma unroll
                        for (int nf = 0; nf < 4; ++nf) {
                            const int col = cbase + nf * 8;
                            const float2 bv = *(const float2*)(brow + col);
                            float v0 = gelu_fast(acc[mf][nf][half * 2 + 0] + bv.x);
                            float v1 = gelu_fast(acc[mf][nf][half * 2 + 1] + bv.y);
                            *(__half2*)(orow + col) = __floats2half2_rn(v0, v1);
                        }
                    } else {
                        const float w = __ldg(wts + slot);
                        float* __restrict__ orow = out + (size_t)(slot >> 1) * D_DIM + n0;
                        #pragma unroll
                        for (int nf = 0; nf < 4; ++nf) {
                            const int col = cbase + nf * 8;
                            const float2 bv = *(const float2*)(brow + col);
                            float v0 = (acc[mf][nf][half * 2 + 0] + bv.x) * w;
                            float v1 = (acc[mf][nf][half * 2 + 1] + bv.y) * w;
                            red_add_v2(orow + col, v0, v1);
                        }
                    }
                }
            }
        }
    }
}

// ---------------- launch ----------------
extern "C" void kernel_launch(void* const* d_in, const int* in_sizes, int n_in,
                              void* d_out, int out_size) {
    const float* hidden = (const float*)d_in[0];
    const int*   idx    = (const int*)d_in[1];
    const float* wts    = (const float*)d_in[2];
    const float* W1     = (const float*)d_in[3];
    const float* b1     = (const float*)d_in[4];
    const float* W2     = (const float*)d_in[5];
    const float* b2     = (const float*)d_in[6];
    float*       out    = (float*)d_out;
    (void)in_sizes; (void)n_in; (void)out_size;

    cudaFuncSetAttribute(moe_gemm_fp16<1>, cudaFuncAttributeMaxDynamicSharedMemorySize, SMEM_BYTES);
    cudaFuncSetAttribute(moe_gemm_fp16<2>, cudaFuncAttributeMaxDynamicSharedMemorySize, SMEM_BYTES);

    zero_counts_kernel<<<1, 32>>>();
    route_kernel<<<NSLOT / 256, 256>>>(idx);

    const int prep_total = NX4 + 2 * NWC + NX4;
    prep_kernel<<<(prep_total + 255) / 256, 256>>>(hidden, W1, W2, out);

    moe_gemm_fp16<1><<<NCTA, NTHREADS, SMEM_BYTES>>>(b1, nullptr, nullptr);
    moe_gemm_fp16<2><<<NCTA, NTHREADS, SMEM_BYTES>>>(b2, wts, out);
}